// round 1
// baseline (speedup 1.0000x reference)
#include <cuda_runtime.h>
#include <math.h>

#define B_ 4
#define T_ 2048
#define C_ 768
#define H_ 16
#define D_ 48

// ---------------- scratch (static device globals; no allocation) ----------------
__device__ float g_qh[B_*H_*T_*D_];   // Q, roped, [B,H,T,D]
__device__ float g_kh[B_*H_*T_*D_];   // K, roped, [B,H,T,D]
__device__ float g_vh[B_*H_*T_*D_];   // V,        [B,H,T,D]
__device__ float g_ctx[B_*T_*C_];     // attention output, [B,T,C]
__device__ float g_cos[T_*D_];
__device__ float g_sin[T_*D_];

// ---------------- RoPE table (fp64 for accuracy; runs once per launch) ----------
__global__ void rope_table_kernel() {
    int i = blockIdx.x * blockDim.x + threadIdx.x;
    if (i >= T_ * D_) return;
    int t = i / D_, d = i % D_;
    int p = (d < D_/2) ? d : d - D_/2;
    double inv = exp(-(2.0 * p / (double)D_) * log(10000.0));
    double ang = (double)t * inv;
    g_cos[i] = (float)cos(ang);
    g_sin[i] = (float)sin(ang);
}

// ---------------- fused QKV projection + bias + RoPE + head-transpose -----------
// grid: (BT/64, H, 3)  block: 256
// Each CTA computes a [64 x 48] tile = 64 tokens x one head, for q/k/v.
__global__ __launch_bounds__(256) void qkv_proj_kernel(
    const float* __restrict__ X,
    const float* __restrict__ Wq, const float* __restrict__ bq,
    const float* __restrict__ Wk, const float* __restrict__ bk,
    const float* __restrict__ Wv, const float* __restrict__ bv)
{
    const int mt = blockIdx.x, h = blockIdx.y, which = blockIdx.z;
    const float* W    = (which == 0) ? Wq : ((which == 1) ? Wk : Wv);
    const float* bias = (which == 0) ? bq : ((which == 1) ? bk : bv);
    float* out        = (which == 0) ? g_qh : ((which == 1) ? g_kh : g_vh);

    __shared__ float As[16][65];   // X tile, transposed: As[k][m]
    __shared__ float Bs[16][49];   // W tile:             Bs[k][n]
    __shared__ float Cs[64][49];   // raw result for RoPE pairing

    const int tid = threadIdx.x;
    const int ty = tid >> 4, tx = tid & 15;   // 16x16 threads, 4 rows x 3 cols each
    const int row0 = mt * 64, col0 = h * 48;

    float acc[4][3] = {};
    for (int k0 = 0; k0 < C_; k0 += 16) {
        #pragma unroll
        for (int i = 0; i < 4; i++) {              // 64*16 = 1024 = 4*256
            int idx = tid + i * 256;
            int m = idx >> 4, kk = idx & 15;
            As[kk][m] = X[(size_t)(row0 + m) * C_ + k0 + kk];
        }
        #pragma unroll
        for (int i = 0; i < 3; i++) {              // 48*16 = 768 = 3*256
            int idx = tid + i * 256;
            int n = idx >> 4, kk = idx & 15;
            Bs[kk][n] = W[(size_t)(col0 + n) * C_ + k0 + kk];
        }
        __syncthreads();
        #pragma unroll
        for (int kk = 0; kk < 16; kk++) {
            float a[4], bb[3];
            #pragma unroll
            for (int i = 0; i < 4; i++) a[i] = As[kk][4*ty + i];
            #pragma unroll
            for (int j = 0; j < 3; j++) bb[j] = Bs[kk][3*tx + j];
            #pragma unroll
            for (int i = 0; i < 4; i++)
                #pragma unroll
                for (int j = 0; j < 3; j++)
                    acc[i][j] = fmaf(a[i], bb[j], acc[i][j]);
        }
        __syncthreads();
    }

    // bias + stage for RoPE pairing
    #pragma unroll
    for (int i = 0; i < 4; i++)
        #pragma unroll
        for (int j = 0; j < 3; j++)
            Cs[4*ty + i][3*tx + j] = acc[i][j] + bias[col0 + 3*tx + j];
    __syncthreads();

    #pragma unroll
    for (int i = 0; i < 4; i++) {
        int m = 4*ty + i;
        int grow = row0 + m;
        int b = grow >> 11;            // T_ = 2048
        int t = grow & (T_ - 1);
        #pragma unroll
        for (int j = 0; j < 3; j++) {
            int d = 3*tx + j;
            float x = Cs[m][d];
            float val;
            if (which == 2) {
                val = x;               // V: no rope
            } else {
                float c = g_cos[t * D_ + d];
                float s = g_sin[t * D_ + d];
                float partner = (d < D_/2) ? Cs[m][d + D_/2] : Cs[m][d - D_/2];
                val = (d < D_/2) ? (x * c - partner * s) : (x * c + partner * s);
            }
            out[((size_t)((b * H_ + h) * T_ + t)) * D_ + d] = val;
        }
    }
}

// ---------------- streaming (flash-style) causal attention ----------------------
// grid: (T/64, B*H)  block: 256
// Q tile 64x48 in smem; loop key blocks kj <= qi; K buffer reused as P buffer.
__global__ __launch_bounds__(256) void attn_kernel(const float* __restrict__ amask)
{
    const int qi = gridDim.x - 1 - blockIdx.x;   // big blocks first (tail balance)
    const int bh = blockIdx.y;
    const int b = bh >> 4;
    const int h = bh & 15;
    const float* Q = g_qh + (size_t)bh * T_ * D_;
    const float* K = g_kh + (size_t)bh * T_ * D_;
    const float* V = g_vh + (size_t)bh * T_ * D_;

    __shared__ float Qs[64][48];     // broadcast-pattern reads: stride OK
    __shared__ float KP[64][65];     // K tile, then reused to hold P
    __shared__ float Vs[64][48];

    const int tid = threadIdx.x;
    const int ty = tid >> 4, tx = tid & 15;

    #pragma unroll
    for (int i = 0; i < 12; i++) {   // 64*48 = 3072 = 12*256
        int idx = tid + i * 256;
        int r = idx / 48, d = idx % 48;
        Qs[r][d] = Q[(size_t)(qi * 64 + r) * D_ + d];
    }

    float o[4][3] = {};
    float m_i[4], l_i[4] = {};
    #pragma unroll
    for (int i = 0; i < 4; i++) m_i[i] = -INFINITY;
    const float scale = rsqrtf((float)D_);

    for (int kj = 0; kj <= qi; kj++) {
        __syncthreads();   // prev-iter readers of KP/Vs done; also covers Qs on iter 0
        #pragma unroll
        for (int i = 0; i < 12; i++) {
            int idx = tid + i * 256;
            int r = idx / 48, d = idx % 48;
            KP[r][d] = K[(size_t)(kj * 64 + r) * D_ + d];
            Vs[r][d] = V[(size_t)(kj * 64 + r) * D_ + d];
        }
        __syncthreads();

        // S = Q K^T : each thread 4x4
        float s[4][4] = {};
        #pragma unroll
        for (int kk = 0; kk < 48; kk++) {
            float a[4], bb[4];
            #pragma unroll
            for (int i = 0; i < 4; i++) a[i] = Qs[4*ty + i][kk];
            #pragma unroll
            for (int j = 0; j < 4; j++) bb[j] = KP[4*tx + j][kk];
            #pragma unroll
            for (int i = 0; i < 4; i++)
                #pragma unroll
                for (int j = 0; j < 4; j++)
                    s[i][j] = fmaf(a[i], bb[j], s[i][j]);
        }

        // scale + additive padding mask + causal
        float ma[4];
        #pragma unroll
        for (int j = 0; j < 4; j++)
            ma[j] = (1.0f - amask[b * T_ + kj * 64 + 4*tx + j]) * -10000.0f;
        #pragma unroll
        for (int i = 0; i < 4; i++) {
            int qrow = qi * 64 + 4*ty + i;
            #pragma unroll
            for (int j = 0; j < 4; j++) {
                int kcol = kj * 64 + 4*tx + j;
                float sv = s[i][j] * scale + ma[j];
                s[i][j] = (kcol > qrow) ? -INFINITY : sv;
            }
        }

        // row max over the 16-lane (tx) group
        float rmax[4];
        #pragma unroll
        for (int i = 0; i < 4; i++)
            rmax[i] = fmaxf(fmaxf(s[i][0], s[i][1]), fmaxf(s[i][2], s[i][3]));
        #pragma unroll
        for (int off = 8; off >= 1; off >>= 1)
            #pragma unroll
            for (int i = 0; i < 4; i++)
                rmax[i] = fmaxf(rmax[i], __shfl_xor_sync(0xffffffffu, rmax[i], off, 16));

        float corr[4], rsum[4];
        #pragma unroll
        for (int i = 0; i < 4; i++) {
            float mnew = fmaxf(m_i[i], rmax[i]);
            corr[i] = __expf(m_i[i] - mnew);   // exp(-inf)=0 on first block
            m_i[i] = mnew;
            float rs = 0.f;
            #pragma unroll
            for (int j = 0; j < 4; j++) {
                s[i][j] = __expf(s[i][j] - mnew);
                rs += s[i][j];
            }
            rsum[i] = rs;
        }
        #pragma unroll
        for (int off = 8; off >= 1; off >>= 1)
            #pragma unroll
            for (int i = 0; i < 4; i++)
                rsum[i] += __shfl_xor_sync(0xffffffffu, rsum[i], off, 16);

        #pragma unroll
        for (int i = 0; i < 4; i++) {
            l_i[i] = l_i[i] * corr[i] + rsum[i];
            #pragma unroll
            for (int c = 0; c < 3; c++) o[i][c] *= corr[i];
        }

        // P -> reuse K buffer (all S reads of KP are done; fence it)
        __syncthreads();
        #pragma unroll
        for (int i = 0; i < 4; i++)
            #pragma unroll
            for (int j = 0; j < 4; j++)
                KP[4*ty + i][4*tx + j] = s[i][j];
        __syncthreads();

        // O += P @ V : each thread 4 rows x 3 cols
        #pragma unroll 4
        for (int j = 0; j < 64; j++) {
            float pv[4], vv[3];
            #pragma unroll
            for (int i = 0; i < 4; i++) pv[i] = KP[4*ty + i][j];
            #pragma unroll
            for (int c = 0; c < 3; c++) vv[c] = Vs[j][3*tx + c];
            #pragma unroll
            for (int i = 0; i < 4; i++)
                #pragma unroll
                for (int c = 0; c < 3; c++)
                    o[i][c] = fmaf(pv[i], vv[c], o[i][c]);
        }
    }

    // normalize + write ctx in [B,T,C] layout (ready for out-proj)
    #pragma unroll
    for (int i = 0; i < 4; i++) {
        int t = qi * 64 + 4*ty + i;
        float inv_l = 1.0f / l_i[i];
        #pragma unroll
        for (int c = 0; c < 3; c++) {
            int d = 3*tx + c;
            g_ctx[(size_t)(b * T_ + t) * C_ + h * D_ + d] = o[i][c] * inv_l;
        }
    }
}

// ---------------- output projection: out = ctx @ Wo^T + bo ----------------------
// grid: (BT/64, C/64)  block: 256
__global__ __launch_bounds__(256) void out_proj_kernel(
    const float* __restrict__ Wo, const float* __restrict__ bo,
    float* __restrict__ out)
{
    const int mt = blockIdx.x, nt = blockIdx.y;
    __shared__ float As[16][65];
    __shared__ float Bs[16][65];
    const int tid = threadIdx.x;
    const int ty = tid >> 4, tx = tid & 15;
    const int row0 = mt * 64, col0 = nt * 64;

    float acc[4][4] = {};
    for (int k0 = 0; k0 < C_; k0 += 16) {
        #pragma unroll
        for (int i = 0; i < 4; i++) {
            int idx = tid + i * 256;
            int m = idx >> 4, kk = idx & 15;
            As[kk][m] = g_ctx[(size_t)(row0 + m) * C_ + k0 + kk];
            Bs[kk][m] = Wo  [(size_t)(col0 + m) * C_ + k0 + kk];
        }
        __syncthreads();
        #pragma unroll
        for (int kk = 0; kk < 16; kk++) {
            float a[4], bb[4];
            #pragma unroll
            for (int i = 0; i < 4; i++) a[i] = As[kk][4*ty + i];
            #pragma unroll
            for (int j = 0; j < 4; j++) bb[j] = Bs[kk][4*tx + j];
            #pragma unroll
            for (int i = 0; i < 4; i++)
                #pragma unroll
                for (int j = 0; j < 4; j++)
                    acc[i][j] = fmaf(a[i], bb[j], acc[i][j]);
        }
        __syncthreads();
    }
    #pragma unroll
    for (int i = 0; i < 4; i++)
        #pragma unroll
        for (int j = 0; j < 4; j++)
            out[(size_t)(row0 + 4*ty + i) * C_ + col0 + 4*tx + j] =
                acc[i][j] + bo[col0 + 4*tx + j];
}

// ---------------- launch -------------------------------------------------------
extern "C" void kernel_launch(void* const* d_in, const int* in_sizes, int n_in,
                              void* d_out, int out_size)
{
    const float* X     = (const float*)d_in[0];
    const float* amask = (const float*)d_in[1];
    const float* Wq    = (const float*)d_in[2];
    const float* bq    = (const float*)d_in[3];
    const float* Wk    = (const float*)d_in[4];
    const float* bk    = (const float*)d_in[5];
    const float* Wv    = (const float*)d_in[6];
    const float* bv    = (const float*)d_in[7];
    const float* Wo    = (const float*)d_in[8];
    const float* bo    = (const float*)d_in[9];
    float* out = (float*)d_out;

    rope_table_kernel<<<(T_ * D_ + 255) / 256, 256>>>();
    qkv_proj_kernel<<<dim3((B_ * T_) / 64, H_, 3), 256>>>(X, Wq, bq, Wk, bk, Wv, bv);
    attn_kernel<<<dim3(T_ / 64, B_ * H_), 256>>>(amask);
    out_proj_kernel<<<dim3((B_ * T_) / 64, C_ / 64), 256>>>(Wo, bo, out);
}

// round 4
// speedup vs baseline: 3.4827x; 3.4827x over previous
#include <cuda_runtime.h>
#include <math.h>
#include <stdint.h>

#define B_ 4
#define T_ 2048
#define C_ 768
#define H_ 16
#define D_ 48

// ---------------- scratch (static device globals; no allocation) ----------------
__device__ float g_qh[B_*H_*T_*D_];   // Q, roped, [B,H,T,D]
__device__ float g_kh[B_*H_*T_*D_];   // K, roped, [B,H,T,D]
__device__ float g_vh[B_*H_*T_*D_];   // V,        [B,H,T,D]
__device__ float g_ctx[B_*T_*C_];     // attention output, [B,T,C]
__device__ float g_cos[T_*D_];
__device__ float g_sin[T_*D_];

// ---------------- helpers -------------------------------------------------------
__device__ __forceinline__ float to_tf32(float x) {
    uint32_t u;
    asm("cvt.rna.tf32.f32 %0, %1;" : "=r"(u) : "f"(x));
    return __uint_as_float(u);
}

// d += a * b   (m16n8k8, tf32 inputs as f32 bit patterns, f32 accum)
__device__ __forceinline__ void mma_tf32(float* d, const float* a, const float* b) {
    asm volatile(
        "mma.sync.aligned.m16n8k8.row.col.f32.tf32.tf32.f32 "
        "{%0,%1,%2,%3}, {%4,%5,%6,%7}, {%8,%9}, {%0,%1,%2,%3};\n"
        : "+f"(d[0]), "+f"(d[1]), "+f"(d[2]), "+f"(d[3])
        : "r"(__float_as_uint(a[0])), "r"(__float_as_uint(a[1])),
          "r"(__float_as_uint(a[2])), "r"(__float_as_uint(a[3])),
          "r"(__float_as_uint(b[0])), "r"(__float_as_uint(b[1])));
}

// ---------------- RoPE table (fp64 for accuracy) --------------------------------
__global__ void rope_table_kernel() {
    int i = blockIdx.x * blockDim.x + threadIdx.x;
    if (i >= T_ * D_) return;
    int t = i / D_, d = i % D_;
    int p = (d < D_/2) ? d : d - D_/2;
    double inv = exp(-(2.0 * p / (double)D_) * log(10000.0));
    double ang = (double)t * inv;
    g_cos[i] = (float)cos(ang);
    g_sin[i] = (float)sin(ang);
}

// ---------------- fused QKV projection + bias + RoPE (tf32 mma) -----------------
// grid: (BT/64, H, 3)  block: 128 (4 warps). Tile: 64 x 48 (one head), K-chunk 32.
__global__ __launch_bounds__(128) void qkv_proj_kernel(
    const float* __restrict__ X,
    const float* __restrict__ Wq, const float* __restrict__ bq,
    const float* __restrict__ Wk, const float* __restrict__ bk,
    const float* __restrict__ Wv, const float* __restrict__ bv)
{
    const int mt = blockIdx.x, h = blockIdx.y, which = blockIdx.z;
    const float* W    = (which == 0) ? Wq : ((which == 1) ? Wk : Wv);
    const float* bias = (which == 0) ? bq : ((which == 1) ? bk : bv);
    float* out        = (which == 0) ? g_qh : ((which == 1) ? g_kh : g_vh);

    __shared__ float As[64][36];   // X tile (tf32-rounded), stride 36 -> conflict-free frags
    __shared__ float Bs[48][36];   // W tile

    const int tid  = threadIdx.x;
    const int lane = tid & 31;
    const int w    = tid >> 5;
    const int row0 = mt * 64, col0 = h * 48;
    const int g    = lane >> 2;      // group id (row within fragment)
    const int tg   = lane & 3;       // thread-in-group (col within fragment)

    float acc[6][4] = {};

    for (int k0 = 0; k0 < C_; k0 += 32) {
        #pragma unroll
        for (int i = 0; i < 4; i++) {              // 64x32 = 512 float4
            int idx = tid + i * 128;
            int r = idx >> 3, c4 = (idx & 7) * 4;
            float4 v = *(const float4*)&X[(size_t)(row0 + r) * C_ + k0 + c4];
            As[r][c4+0] = to_tf32(v.x); As[r][c4+1] = to_tf32(v.y);
            As[r][c4+2] = to_tf32(v.z); As[r][c4+3] = to_tf32(v.w);
        }
        #pragma unroll
        for (int i = 0; i < 3; i++) {              // 48x32 = 384 float4
            int idx = tid + i * 128;
            int r = idx >> 3, c4 = (idx & 7) * 4;
            float4 v = *(const float4*)&W[(size_t)(col0 + r) * C_ + k0 + c4];
            Bs[r][c4+0] = to_tf32(v.x); Bs[r][c4+1] = to_tf32(v.y);
            Bs[r][c4+2] = to_tf32(v.z); Bs[r][c4+3] = to_tf32(v.w);
        }
        __syncthreads();
        #pragma unroll
        for (int ks = 0; ks < 4; ks++) {
            float a[4];
            int ar = w * 16 + g, ac = ks * 8 + tg;
            a[0] = As[ar][ac];     a[1] = As[ar+8][ac];
            a[2] = As[ar][ac+4];   a[3] = As[ar+8][ac+4];
            #pragma unroll
            for (int nf = 0; nf < 6; nf++) {
                float bf[2];
                int br = nf * 8 + g, bc = ks * 8 + tg;
                bf[0] = Bs[br][bc]; bf[1] = Bs[br][bc+4];
                mma_tf32(acc[nf], a, bf);
            }
        }
        __syncthreads();
    }

    // epilogue: bias + RoPE fully in registers (pair d <-> d+24 == frag nf <-> nf+3)
    #pragma unroll
    for (int half = 0; half < 2; half++) {
        int grow = row0 + w * 16 + g + half * 8;
        int b = grow >> 11;             // T_ = 2048
        int t = grow & (T_ - 1);
        size_t base = ((size_t)((b * H_ + h) * T_) + t) * D_;
        if (which == 2) {
            #pragma unroll
            for (int nf = 0; nf < 6; nf++) {
                int d = nf * 8 + 2 * tg;
                float2 v;
                v.x = acc[nf][2*half+0] + bias[col0 + d];
                v.y = acc[nf][2*half+1] + bias[col0 + d + 1];
                *(float2*)&out[base + d] = v;
            }
        } else {
            #pragma unroll
            for (int nf = 0; nf < 3; nf++) {
                int d = nf * 8 + 2 * tg;
                float c0 = g_cos[t * D_ + d],     s0 = g_sin[t * D_ + d];
                float c1 = g_cos[t * D_ + d + 1], s1 = g_sin[t * D_ + d + 1];
                float x1a = acc[nf  ][2*half+0] + bias[col0 + d];
                float x1b = acc[nf  ][2*half+1] + bias[col0 + d + 1];
                float x2a = acc[nf+3][2*half+0] + bias[col0 + d + 24];
                float x2b = acc[nf+3][2*half+1] + bias[col0 + d + 25];
                float2 lo, hi;
                lo.x = x1a * c0 - x2a * s0;  lo.y = x1b * c1 - x2b * s1;
                hi.x = x2a * c0 + x1a * s0;  hi.y = x2b * c1 + x1b * s1;
                *(float2*)&out[base + d]      = lo;
                *(float2*)&out[base + d + 24] = hi;
            }
        }
    }
}

// ---------------- flash-style causal attention (tf32 mma) -----------------------
// grid: (T/64, B*H)  block: 128 (4 warps). S tile 64x64, D=48 resident.
// KP stride 68: holds K tile (64x48) then P tile (64x64). 68 mod 32 = 4 keeps the
// quad fragment accesses (bank = 4g+tg) conflict-free, and 8*68 = 0 mod 32.
__global__ __launch_bounds__(128) void attn_kernel(const float* __restrict__ amask)
{
    const int qi = gridDim.x - 1 - blockIdx.x;
    const int bh = blockIdx.y;
    const int b = bh >> 4;
    const float* Q = g_qh + (size_t)bh * T_ * D_;
    const float* K = g_kh + (size_t)bh * T_ * D_;
    const float* V = g_vh + (size_t)bh * T_ * D_;

    __shared__ float Qs[64][52];   // stride 52 -> conflict-free A frag loads
    __shared__ float KP[64][68];   // K tile (48 cols) / P tile (64 cols)
    __shared__ float Vs[64][56];   // stride 56 -> conflict-free B frag loads
    __shared__ float Ms[64];       // additive padding mask for current key block

    const int tid  = threadIdx.x;
    const int lane = tid & 31;
    const int w    = tid >> 5;
    const int g    = lane >> 2;
    const int tg   = lane & 3;

    #pragma unroll
    for (int i = 0; i < 6; i++) {            // 64x48 = 768 float4
        int idx = tid + i * 128;
        int r = idx / 12, c4 = (idx % 12) * 4;
        float4 v = *(const float4*)&Q[(size_t)(qi * 64 + r) * D_ + c4];
        Qs[r][c4+0] = to_tf32(v.x); Qs[r][c4+1] = to_tf32(v.y);
        Qs[r][c4+2] = to_tf32(v.z); Qs[r][c4+3] = to_tf32(v.w);
    }

    float m_i[2], l_i[2] = {0.f, 0.f};
    m_i[0] = -INFINITY; m_i[1] = -INFINITY;
    float o[6][4] = {};
    const float scale = rsqrtf((float)D_);

    for (int kj = 0; kj <= qi; kj++) {
        __syncthreads();   // prior readers of KP/Vs done; also covers Qs writes on iter 0
        #pragma unroll
        for (int i = 0; i < 6; i++) {
            int idx = tid + i * 128;
            int r = idx / 12, c4 = (idx % 12) * 4;
            float4 kv = *(const float4*)&K[(size_t)(kj * 64 + r) * D_ + c4];
            float4 vv = *(const float4*)&V[(size_t)(kj * 64 + r) * D_ + c4];
            KP[r][c4+0] = to_tf32(kv.x); KP[r][c4+1] = to_tf32(kv.y);
            KP[r][c4+2] = to_tf32(kv.z); KP[r][c4+3] = to_tf32(kv.w);
            Vs[r][c4+0] = to_tf32(vv.x); Vs[r][c4+1] = to_tf32(vv.y);
            Vs[r][c4+2] = to_tf32(vv.z); Vs[r][c4+3] = to_tf32(vv.w);
        }
        if (tid < 64) Ms[tid] = (1.0f - amask[b * T_ + kj * 64 + tid]) * -10000.0f;
        __syncthreads();

        // ---- S = Q K^T (scaled later) ----
        float s[8][4] = {};
        #pragma unroll
        for (int ks = 0; ks < 6; ks++) {
            float a[4];
            int ar = w * 16 + g, ac = ks * 8 + tg;
            a[0] = Qs[ar][ac];   a[1] = Qs[ar+8][ac];
            a[2] = Qs[ar][ac+4]; a[3] = Qs[ar+8][ac+4];
            #pragma unroll
            for (int nf = 0; nf < 8; nf++) {
                float bf[2];
                int br = nf * 8 + g, bc = ks * 8 + tg;
                bf[0] = KP[br][bc]; bf[1] = KP[br][bc+4];
                mma_tf32(s[nf], a, bf);
            }
        }

        // ---- scale + masks + online softmax ----
        const int qrow0 = qi * 64 + w * 16 + g;  // row for half=0; +8 for half=1
        float rmax[2];
        rmax[0] = -INFINITY; rmax[1] = -INFINITY;
        #pragma unroll
        for (int nf = 0; nf < 8; nf++) {
            int kc  = kj * 64 + nf * 8 + 2 * tg;
            float ma0 = Ms[nf * 8 + 2 * tg];
            float ma1 = Ms[nf * 8 + 2 * tg + 1];
            #pragma unroll
            for (int half = 0; half < 2; half++) {
                int qr = qrow0 + half * 8;
                float v0 = s[nf][2*half+0] * scale + ma0;
                float v1 = s[nf][2*half+1] * scale + ma1;
                v0 = (kc     > qr) ? -INFINITY : v0;
                v1 = (kc + 1 > qr) ? -INFINITY : v1;
                s[nf][2*half+0] = v0; s[nf][2*half+1] = v1;
                rmax[half] = fmaxf(rmax[half], fmaxf(v0, v1));
            }
        }
        #pragma unroll
        for (int off = 1; off <= 2; off <<= 1) {
            rmax[0] = fmaxf(rmax[0], __shfl_xor_sync(0xffffffffu, rmax[0], off));
            rmax[1] = fmaxf(rmax[1], __shfl_xor_sync(0xffffffffu, rmax[1], off));
        }

        float corr[2], rsum[2] = {0.f, 0.f};
        #pragma unroll
        for (int half = 0; half < 2; half++) {
            float mnew = fmaxf(m_i[half], rmax[half]);
            corr[half] = __expf(m_i[half] - mnew);   // exp(-inf)=0 on first block
            m_i[half] = mnew;
        }
        #pragma unroll
        for (int nf = 0; nf < 8; nf++) {
            #pragma unroll
            for (int half = 0; half < 2; half++) {
                float v0 = __expf(s[nf][2*half+0] - m_i[half]);
                float v1 = __expf(s[nf][2*half+1] - m_i[half]);
                s[nf][2*half+0] = v0; s[nf][2*half+1] = v1;
                rsum[half] += v0 + v1;
            }
        }
        #pragma unroll
        for (int off = 1; off <= 2; off <<= 1) {
            rsum[0] += __shfl_xor_sync(0xffffffffu, rsum[0], off);
            rsum[1] += __shfl_xor_sync(0xffffffffu, rsum[1], off);
        }
        #pragma unroll
        for (int half = 0; half < 2; half++) {
            l_i[half] = l_i[half] * corr[half] + rsum[half];
        }
        #pragma unroll
        for (int nf = 0; nf < 6; nf++) {
            o[nf][0] *= corr[0]; o[nf][1] *= corr[0];
            o[nf][2] *= corr[1]; o[nf][3] *= corr[1];
        }

        // ---- P -> KP (all S-mma reads of KP are complete) ----
        __syncthreads();
        {
            int pr = w * 16 + g;
            #pragma unroll
            for (int nf = 0; nf < 8; nf++) {
                int pc = nf * 8 + 2 * tg;
                float2 lo, hi;
                lo.x = to_tf32(s[nf][0]); lo.y = to_tf32(s[nf][1]);
                hi.x = to_tf32(s[nf][2]); hi.y = to_tf32(s[nf][3]);
                *(float2*)&KP[pr    ][pc] = lo;
                *(float2*)&KP[pr + 8][pc] = hi;
            }
        }
        __syncthreads();

        // ---- O += P V ----
        #pragma unroll
        for (int ks = 0; ks < 8; ks++) {
            float a[4];
            int ar = w * 16 + g, ac = ks * 8 + tg;
            a[0] = KP[ar][ac];   a[1] = KP[ar+8][ac];
            a[2] = KP[ar][ac+4]; a[3] = KP[ar+8][ac+4];
            #pragma unroll
            for (int nf = 0; nf < 6; nf++) {
                float bf[2];
                int vr = ks * 8 + tg, vc = nf * 8 + g;
                bf[0] = Vs[vr][vc]; bf[1] = Vs[vr + 4][vc];
                mma_tf32(o[nf], a, bf);
            }
        }
    }

    // ---- normalize + write ctx [B,T,C] ----
    const int h = bh & 15;
    float invl[2] = {1.0f / l_i[0], 1.0f / l_i[1]};
    #pragma unroll
    for (int half = 0; half < 2; half++) {
        int t = qi * 64 + w * 16 + g + half * 8;
        size_t base = (size_t)(b * T_ + t) * C_ + h * D_;
        #pragma unroll
        for (int nf = 0; nf < 6; nf++) {
            int d = nf * 8 + 2 * tg;
            float2 v;
            v.x = o[nf][2*half+0] * invl[half];
            v.y = o[nf][2*half+1] * invl[half];
            *(float2*)&g_ctx[base + d] = v;
        }
    }
}

// ---------------- output projection: out = ctx @ Wo^T + bo (tf32 mma) -----------
// grid: (BT/64, C/64)  block: 128. Tile 64x64, K-chunk 32. Warp: 16 rows x 64 cols.
__global__ __launch_bounds__(128) void out_proj_kernel(
    const float* __restrict__ Wo, const float* __restrict__ bo,
    float* __restrict__ out)
{
    const int mt = blockIdx.x, nt = blockIdx.y;
    __shared__ float As[64][36];
    __shared__ float Bs[64][36];

    const int tid  = threadIdx.x;
    const int lane = tid & 31;
    const int w    = tid >> 5;
    const int g    = lane >> 2;
    const int tg   = lane & 3;
    const int row0 = mt * 64, col0 = nt * 64;

    float acc[8][4] = {};

    for (int k0 = 0; k0 < C_; k0 += 32) {
        #pragma unroll
        for (int i = 0; i < 4; i++) {
            int idx = tid + i * 128;
            int r = idx >> 3, c4 = (idx & 7) * 4;
            float4 va = *(const float4*)&g_ctx[(size_t)(row0 + r) * C_ + k0 + c4];
            float4 vb = *(const float4*)&Wo  [(size_t)(col0 + r) * C_ + k0 + c4];
            As[r][c4+0] = to_tf32(va.x); As[r][c4+1] = to_tf32(va.y);
            As[r][c4+2] = to_tf32(va.z); As[r][c4+3] = to_tf32(va.w);
            Bs[r][c4+0] = to_tf32(vb.x); Bs[r][c4+1] = to_tf32(vb.y);
            Bs[r][c4+2] = to_tf32(vb.z); Bs[r][c4+3] = to_tf32(vb.w);
        }
        __syncthreads();
        #pragma unroll
        for (int ks = 0; ks < 4; ks++) {
            float a[4];
            int ar = w * 16 + g, ac = ks * 8 + tg;
            a[0] = As[ar][ac];   a[1] = As[ar+8][ac];
            a[2] = As[ar][ac+4]; a[3] = As[ar+8][ac+4];
            #pragma unroll
            for (int nf = 0; nf < 8; nf++) {
                float bf[2];
                int br = nf * 8 + g, bc = ks * 8 + tg;
                bf[0] = Bs[br][bc]; bf[1] = Bs[br][bc+4];
                mma_tf32(acc[nf], a, bf);
            }
        }
        __syncthreads();
    }

    #pragma unroll
    for (int half = 0; half < 2; half++) {
        int r = row0 + w * 16 + g + half * 8;
        #pragma unroll
        for (int nf = 0; nf < 8; nf++) {
            int c = col0 + nf * 8 + 2 * tg;
            float2 v;
            v.x = acc[nf][2*half+0] + bo[c];
            v.y = acc[nf][2*half+1] + bo[c + 1];
            *(float2*)&out[(size_t)r * C_ + c] = v;
        }
    }
}

// ---------------- launch -------------------------------------------------------
extern "C" void kernel_launch(void* const* d_in, const int* in_sizes, int n_in,
                              void* d_out, int out_size)
{
    const float* X     = (const float*)d_in[0];
    const float* amask = (const float*)d_in[1];
    const float* Wq    = (const float*)d_in[2];
    const float* bq    = (const float*)d_in[3];
    const float* Wk    = (const float*)d_in[4];
    const float* bk    = (const float*)d_in[5];
    const float* Wv    = (const float*)d_in[6];
    const float* bv    = (const float*)d_in[7];
    const float* Wo    = (const float*)d_in[8];
    const float* bo    = (const float*)d_in[9];
    float* out = (float*)d_out;

    rope_table_kernel<<<(T_ * D_ + 255) / 256, 256>>>();
    qkv_proj_kernel<<<dim3((B_ * T_) / 64, H_, 3), 128>>>(X, Wq, bq, Wk, bk, Wv, bv);
    attn_kernel<<<dim3(T_ / 64, B_ * H_), 128>>>(amask);
    out_proj_kernel<<<dim3((B_ * T_) / 64, C_ / 64), 128>>>(Wo, bo, out);
}